// round 11
// baseline (speedup 1.0000x reference)
#include <cuda_runtime.h>
#include <cuda_bf16.h>
#include <math.h>
#include <stdint.h>

#define HEADS   12
#define DMODEL  768
#define HDIM    64
#define BATCH   2
#define SEQ     2048
#define ROWS    4096
#define BH      24
#define NEGBIG  (-3.402823e38f)

static const long long OUT_ELEMS = (long long)ROWS * DMODEL;
static const long long W_ELEMS   = (long long)BH * SEQ * SEQ;

#define XN (ROWS * DMODEL)
#define WNN (DMODEL * DMODEL)

// Scratch (device globals: allocation-free)
__device__ __nv_bfloat16 g_xh[3][XN], g_xl[3][XN];
__device__ __nv_bfloat16 g_wh[4][WNN], g_wl[4][WNN];
__device__ __nv_bfloat16 g_Qh[XN], g_Ql[XN];
__device__ __nv_bfloat16 g_Kh[XN], g_Kl[XN];
__device__ __nv_bfloat16 g_Vh[XN], g_Vl[XN];         // [b,h,dh,s]
__device__ __nv_bfloat16 g_ch[XN], g_cl[XN];
__device__ float  g_cp[2][XN];
__device__ float2 g_ps[BH * 16 * SEQ];
__device__ float  g_ssc[(long long)BH * SEQ * SEQ];  // raw scores scratch
__device__ float  g_wsc[(long long)BH * SEQ * SEQ];  // weights fallback
__device__ float  g_osc[XN];

struct ProjArgs {
    const __nv_bfloat16 *Ah[3], *Al[3], *Bh[3], *Bl[3];
    const float* bias[3];
    __nv_bfloat16 *oh[3], *ol[3];
};
struct SplitSeg { const float* src; __nv_bfloat16* hi; __nv_bfloat16* lo; int n4; };
struct SplitArgs { SplitSeg seg[7]; };

__device__ __forceinline__ uint32_t smem_u32(const void* p) {
    return (uint32_t)__cvta_generic_to_shared(p);
}
__device__ __forceinline__ void cpa16(uint32_t d, const void* s) {
    asm volatile("cp.async.cg.shared.global [%0], [%1], 16;" :: "r"(d), "l"(s));
}
#define CP_COMMIT() asm volatile("cp.async.commit_group;")
#define CP_WAIT1()  asm volatile("cp.async.wait_group 1;")

__device__ __forceinline__ void mma16816(float* c,
                                         uint32_t a0, uint32_t a1, uint32_t a2, uint32_t a3,
                                         uint32_t b0, uint32_t b1)
{
    asm volatile(
        "mma.sync.aligned.m16n8k16.row.col.f32.bf16.bf16.f32 "
        "{%0,%1,%2,%3}, {%4,%5,%6,%7}, {%8,%9}, {%0,%1,%2,%3};\n"
        : "+f"(c[0]), "+f"(c[1]), "+f"(c[2]), "+f"(c[3])
        : "r"(a0), "r"(a1), "r"(a2), "r"(a3), "r"(b0), "r"(b1));
}

__device__ __forceinline__ void splitstore(__nv_bfloat16* ph, __nv_bfloat16* pl, float4 f)
{
    float xs[4] = {f.x, f.y, f.z, f.w};
#pragma unroll
    for (int p = 0; p < 2; ++p) {
        float x0 = xs[2 * p], x1 = xs[2 * p + 1];
        __nv_bfloat16 h0 = __float2bfloat16(x0);
        __nv_bfloat16 h1 = __float2bfloat16(x1);
        __nv_bfloat16 l0 = __float2bfloat16(x0 - __bfloat162float(h0));
        __nv_bfloat16 l1 = __float2bfloat16(x1 - __bfloat162float(h1));
        __nv_bfloat162 vh; vh.x = h0; vh.y = h1;
        __nv_bfloat162 vl; vl.x = l0; vl.y = l1;
        *(__nv_bfloat162*)(ph + 2 * p) = vh;
        *(__nv_bfloat162*)(pl + 2 * p) = vl;
    }
}

__device__ __forceinline__ void split2(float2 p, uint32_t& hi, uint32_t& lo)
{
    __nv_bfloat16 h0 = __float2bfloat16(p.x);
    __nv_bfloat16 h1 = __float2bfloat16(p.y);
    __nv_bfloat162 hh; hh.x = h0; hh.y = h1;
    __nv_bfloat162 ll;
    ll.x = __float2bfloat16(p.x - __bfloat162float(h0));
    ll.y = __float2bfloat16(p.y - __bfloat162float(h1));
    hi = *(uint32_t*)&hh;
    lo = *(uint32_t*)&ll;
}

// ---------------------------------------------------------------------------
__global__ void split_all(SplitArgs a)
{
    const SplitSeg s = a.seg[blockIdx.y];
    int i = blockIdx.x * 256 + threadIdx.x;
    if (i >= s.n4) return;
    float4 f = ((const float4*)s.src)[i];
    splitstore(s.hi + 4 * (size_t)i, s.lo + 4 * (size_t)i, f);
}

// ---------------------------------------------------------------------------
// Unified bf16x3 GEMM, cp.async double-buffered. C = A[M,K] @ B[N,K]^T.
// Tile 128x128x32, 8 warps (2 m x 4 n).
// MODE 1: fp32 out + bias. MODE 2: scores (scale, mask, raw S + pstat).
// MODE 5: QKV fused (z), outputs pre-split hi/lo; z==2 transposed V.
// ---------------------------------------------------------------------------
#define SP 40

template<int MODE>
__global__ void __launch_bounds__(256)
gemm_bf3(const __nv_bfloat16* __restrict__ Ahg, const __nv_bfloat16* __restrict__ Alg,
         const __nv_bfloat16* __restrict__ Bhg, const __nv_bfloat16* __restrict__ Blg,
         int lda, int ldb, int K,
         float* __restrict__ Cg, const float* __restrict__ biasg,
         const float* __restrict__ maskg, float2* __restrict__ pstat,
         ProjArgs pa)
{
    extern __shared__ __align__(16) char smraw[];
    __nv_bfloat16* sAh = (__nv_bfloat16*)smraw;
    __nv_bfloat16* sAl = sAh + 2 * 128 * SP;
    __nv_bfloat16* sBh = sAl + 2 * 128 * SP;
    __nv_bfloat16* sBl = sBh + 2 * 128 * SP;

    const int tid = threadIdx.x;
    const int wid = tid >> 5, lane = tid & 31;
    const int g = lane >> 2, t = lane & 3;
    const int wm = wid & 1, wn = wid >> 1;
    const int m0 = blockIdx.x * 128, n0 = blockIdx.y * 128;
    const int z  = blockIdx.z;

    const __nv_bfloat16 *Ah, *Al, *Bh, *Bl;
    const float* biasp = biasg;
    if (MODE == 5) {
        Ah = pa.Ah[z]; Al = pa.Al[z]; Bh = pa.Bh[z]; Bl = pa.Bl[z]; biasp = pa.bias[z];
    } else if (MODE == 2) {
        size_t off = (size_t)z * SEQ * HDIM;
        Ah = Ahg + off; Al = Alg + off; Bh = Bhg + off; Bl = Blg + off;
    } else {
        Ah = Ahg; Al = Alg; Bh = Bhg; Bl = Blg;
    }

    const int lrow = tid >> 1;
    const int lch  = (tid & 1) * 2;

    auto issue = [&](int kt, int stg) {
        const int k0 = kt * 32;
        const __nv_bfloat16* gah = Ah + (size_t)(m0 + lrow) * lda + k0 + lch * 8;
        const __nv_bfloat16* gal = Al + (size_t)(m0 + lrow) * lda + k0 + lch * 8;
        const __nv_bfloat16* gbh = Bh + (size_t)(n0 + lrow) * ldb + k0 + lch * 8;
        const __nv_bfloat16* gbl = Bl + (size_t)(n0 + lrow) * ldb + k0 + lch * 8;
        uint32_t o = (uint32_t)((stg * 128 + lrow) * SP + lch * 8) * 2;
        uint32_t dah = smem_u32(sAh) + o, dal = smem_u32(sAl) + o;
        uint32_t dbh = smem_u32(sBh) + o, dbl = smem_u32(sBl) + o;
        cpa16(dah, gah); cpa16(dah + 16, gah + 8);
        cpa16(dal, gal); cpa16(dal + 16, gal + 8);
        cpa16(dbh, gbh); cpa16(dbh + 16, gbh + 8);
        cpa16(dbl, gbl); cpa16(dbl + 16, gbl + 8);
    };

    float acc[4][4][4] = {};

    auto compute = [&](int stg) {
        const __nv_bfloat16* pAh = sAh + stg * 128 * SP;
        const __nv_bfloat16* pAl = sAl + stg * 128 * SP;
        const __nv_bfloat16* pBh = sBh + stg * 128 * SP;
        const __nv_bfloat16* pBl = sBl + stg * 128 * SP;
#pragma unroll
        for (int kb = 0; kb < 32; kb += 16) {
            uint32_t ah[4][4], al[4][4];
#pragma unroll
            for (int f = 0; f < 4; ++f) {
                int rbase = wm * 64 + f * 16 + g;
#pragma unroll
                for (int j = 0; j < 4; ++j) {
                    int rr = rbase + (j & 1) * 8;
                    int cc = kb + 2 * t + (j >> 1) * 8;
                    ah[f][j] = *(const uint32_t*)&pAh[rr * SP + cc];
                    al[f][j] = *(const uint32_t*)&pAl[rr * SP + cc];
                }
            }
#pragma unroll
            for (int nn = 0; nn < 4; ++nn) {
                int rb = wn * 32 + nn * 8 + g;
                uint32_t b0 = *(const uint32_t*)&pBh[rb * SP + kb + 2 * t];
                uint32_t b1 = *(const uint32_t*)&pBh[rb * SP + kb + 2 * t + 8];
                uint32_t c0 = *(const uint32_t*)&pBl[rb * SP + kb + 2 * t];
                uint32_t c1 = *(const uint32_t*)&pBl[rb * SP + kb + 2 * t + 8];
#pragma unroll
                for (int f = 0; f < 4; ++f) {
                    mma16816(acc[f][nn], ah[f][0], ah[f][1], ah[f][2], ah[f][3], b0, b1);
                    mma16816(acc[f][nn], ah[f][0], ah[f][1], ah[f][2], ah[f][3], c0, c1);
                    mma16816(acc[f][nn], al[f][0], al[f][1], al[f][2], al[f][3], b0, b1);
                }
            }
        }
    };

    const int nk = K / 32;
    issue(0, 0); CP_COMMIT();
    if (nk > 1) issue(1, 1);
    CP_COMMIT();
    for (int kt = 0; kt < nk; ++kt) {
        int cur = kt & 1;
        CP_WAIT1();
        __syncthreads();
        compute(cur);
        __syncthreads();
        if (kt + 2 < nk) issue(kt + 2, cur);
        CP_COMMIT();
    }

    // ---------------- epilogues ----------------
    if (MODE == 1) {
#pragma unroll
        for (int f = 0; f < 4; ++f)
#pragma unroll
            for (int nn = 0; nn < 4; ++nn)
#pragma unroll
                for (int i2 = 0; i2 < 2; ++i2) {
                    int m = m0 + wm * 64 + f * 16 + g + i2 * 8;
                    int n = n0 + wn * 32 + nn * 8 + 2 * t;
                    float2 st = {acc[f][nn][i2 * 2 + 0] + biasp[n],
                                 acc[f][nn][i2 * 2 + 1] + biasp[n + 1]};
                    *(float2*)&Cg[(size_t)m * DMODEL + n] = st;
                }
    } else if (MODE == 5) {
#pragma unroll
        for (int f = 0; f < 4; ++f)
#pragma unroll
            for (int nn = 0; nn < 4; ++nn)
#pragma unroll
                for (int i2 = 0; i2 < 2; ++i2) {
                    int m = m0 + wm * 64 + f * 16 + g + i2 * 8;
                    int n = n0 + wn * 32 + nn * 8 + 2 * t;
                    float v0 = acc[f][nn][i2 * 2 + 0] + biasp[n];
                    float v1 = acc[f][nn][i2 * 2 + 1] + biasp[n + 1];
                    int b = m >> 11, s = m & 2047;
                    int h = n >> 6,  dh = n & 63;
                    __nv_bfloat16 h0 = __float2bfloat16(v0);
                    __nv_bfloat16 h1 = __float2bfloat16(v1);
                    __nv_bfloat16 l0 = __float2bfloat16(v0 - __bfloat162float(h0));
                    __nv_bfloat16 l1 = __float2bfloat16(v1 - __bfloat162float(h1));
                    if (z < 2) {
                        size_t idx = (((size_t)(b * HEADS + h)) * SEQ + s) * HDIM + dh;
                        __nv_bfloat162 hh; hh.x = h0; hh.y = h1;
                        __nv_bfloat162 ll; ll.x = l0; ll.y = l1;
                        *(__nv_bfloat162*)&pa.oh[z][idx] = hh;
                        *(__nv_bfloat162*)&pa.ol[z][idx] = ll;
                    } else {
                        size_t base = (((size_t)(b * HEADS + h)) * HDIM + dh) * SEQ + s;
                        pa.oh[2][base]       = h0;
                        pa.oh[2][base + SEQ] = h1;
                        pa.ol[2][base]       = l0;
                        pa.ol[2][base + SEQ] = l1;
                    }
                }
    } else { // MODE 2: raw scores + stats
        const int bidx = z / HEADS;
        float* S = Cg + (size_t)z * SEQ * SEQ;
        float mk[4][2];
#pragma unroll
        for (int nn = 0; nn < 4; ++nn) {
            int gc = n0 + wn * 32 + nn * 8 + 2 * t;
            mk[nn][0] = maskg[bidx * SEQ + gc];
            mk[nn][1] = maskg[bidx * SEQ + gc + 1];
        }
        float pm[8], pls[8];
#pragma unroll
        for (int f = 0; f < 4; ++f)
#pragma unroll
            for (int i2 = 0; i2 < 2; ++i2) {
                int sl = f * 2 + i2;
                int rowl = wm * 64 + f * 16 + g + i2 * 8;
                float vb[8]; bool ok[8];
                float tm = NEGBIG;
#pragma unroll
                for (int nn = 0; nn < 4; ++nn) {
                    int gc = n0 + wn * 32 + nn * 8 + 2 * t;
                    float v0 = acc[f][nn][i2 * 2 + 0] * 0.125f;
                    float v1 = acc[f][nn][i2 * 2 + 1] * 0.125f;
                    bool o0 = (mk[nn][0] == 0.0f);
                    bool o1 = (mk[nn][1] == 0.0f);
                    float2 st;
                    st.x = o0 ? v0 : -INFINITY;
                    st.y = o1 ? v1 : -INFINITY;
                    *(float2*)&S[(size_t)(m0 + rowl) * SEQ + gc] = st;
                    vb[nn * 2 + 0] = v0; ok[nn * 2 + 0] = o0;
                    vb[nn * 2 + 1] = v1; ok[nn * 2 + 1] = o1;
                    if (o0) tm = fmaxf(tm, v0);
                    if (o1) tm = fmaxf(tm, v1);
                }
                float tl = 0.f;
#pragma unroll
                for (int j = 0; j < 8; ++j)
                    if (ok[j]) tl += __expf(vb[j] - tm);
                pm[sl] = tm; pls[sl] = tl;
            }
#pragma unroll
        for (int off2 = 1; off2 <= 2; off2 <<= 1)
#pragma unroll
            for (int sl = 0; sl < 8; ++sl) {
                float om = __shfl_xor_sync(0xffffffffu, pm[sl], off2);
                float ol = __shfl_xor_sync(0xffffffffu, pls[sl], off2);
                float nm = fmaxf(pm[sl], om);
                pls[sl] = pls[sl] * __expf(pm[sl] - nm) + ol * __expf(om - nm);
                pm[sl] = nm;
            }
        float2* sred = (float2*)smraw;
        __syncthreads();
        if (t == 0) {
#pragma unroll
            for (int f = 0; f < 4; ++f)
#pragma unroll
                for (int i2 = 0; i2 < 2; ++i2) {
                    int rowl = wm * 64 + f * 16 + g + i2 * 8;
                    sred[wn * 128 + rowl] = make_float2(pm[f * 2 + i2], pls[f * 2 + i2]);
                }
        }
        __syncthreads();
        if (tid < 128) {
            float m = NEGBIG, l = 0.f;
#pragma unroll
            for (int w = 0; w < 4; ++w) {
                float2 p = sred[w * 128 + tid];
                float nm = fmaxf(m, p.x);
                l = l * __expf(m - nm) + p.y * __expf(p.x - nm);
                m = nm;
            }
            pstat[((size_t)z * 16 + blockIdx.y) * SEQ + m0 + tid] = make_float2(m, l);
        }
    }
}

// ---------------------------------------------------------------------------
// ctx split-K: stats combined in-kernel; raw S fragments read from SSC
// (separate buffer), normalized weights written once to WOUT (no aliasing ->
// no race). bf16 hi/lo packed in-reg; only V in smem -> 68KB -> 3 CTAs/SM.
// ---------------------------------------------------------------------------
#define CSP 136

__global__ void __launch_bounds__(256, 3)
ctx_kernel(const float* __restrict__ SSC, float* __restrict__ WOUT,
           const __nv_bfloat16* __restrict__ vh_g,
           const __nv_bfloat16* __restrict__ vl_g,
           const float2* __restrict__ pstat,
           float* __restrict__ cpart)
{
    extern __shared__ __align__(16) char smraw[];
    __nv_bfloat16* Vh = (__nv_bfloat16*)smraw;          // [2][64][CSP]
    __nv_bfloat16* Vl = Vh + 2 * 64 * CSP;

    const int z = blockIdx.z;
    const int kh = blockIdx.y;
    const int b = z / HEADS, h = z % HEADS;
    const int m0 = blockIdx.x * 64;
    const float* S = SSC + (size_t)z * SEQ * SEQ;
    float* W = WOUT + (size_t)z * SEQ * SEQ;
    const __nv_bfloat16* Vhp = vh_g + (size_t)z * HDIM * SEQ;
    const __nv_bfloat16* Vlp = vl_g + (size_t)z * HDIM * SEQ;

    const int tid = threadIdx.x;
    const int wid = tid >> 5, lane = tid & 31;
    const int g = lane >> 2, t = lane & 3;
    const int wm = wid >> 1, wn = wid & 1;
    const int lr = tid >> 2, q4 = tid & 3;

    const int r0 = wm * 16 + g;
    const int r1 = r0 + 8;

    float mr0 = NEGBIG, ls0 = 0.f, mr1 = NEGBIG, ls1 = 0.f;
    {
        const float2* pr0 = pstat + (size_t)z * 16 * SEQ + m0 + r0;
        const float2* pr1 = pstat + (size_t)z * 16 * SEQ + m0 + r1;
#pragma unroll
        for (int cb = 0; cb < 16; ++cb) {
            float2 p0 = pr0[(size_t)cb * SEQ];
            float2 p1 = pr1[(size_t)cb * SEQ];
            float nm0 = fmaxf(mr0, p0.x);
            ls0 = ls0 * __expf(mr0 - nm0) + p0.y * __expf(p0.x - nm0);
            mr0 = nm0;
            float nm1 = fmaxf(mr1, p1.x);
            ls1 = ls1 * __expf(mr1 - nm1) + p1.y * __expf(p1.x - nm1);
            mr1 = nm1;
        }
    }
    const float invl0 = 1.0f / ls0;
    const float invl1 = 1.0f / ls1;

    auto issueV = [&](int it, int stg) {
        const int k0 = it * 128;
        const __nv_bfloat16* gh = Vhp + (size_t)lr * SEQ + k0 + q4 * 32;
        const __nv_bfloat16* gl = Vlp + (size_t)lr * SEQ + k0 + q4 * 32;
        uint32_t o = (uint32_t)((stg * 64 + lr) * CSP + q4 * 32) * 2;
        uint32_t dh_ = smem_u32(Vh) + o, dl_ = smem_u32(Vl) + o;
#pragma unroll
        for (int j = 0; j < 4; ++j) {
            cpa16(dh_ + j * 16, gh + j * 8);
            cpa16(dl_ + j * 16, gl + j * 8);
        }
    };

    const float* Srow0 = S + (size_t)(m0 + r0) * SEQ;
    const float* Srow1 = S + (size_t)(m0 + r1) * SEQ;
    float* Wrow0 = W + (size_t)(m0 + r0) * SEQ;
    float* Wrow1 = W + (size_t)(m0 + r1) * SEQ;

    auto ldfrag = [&](float2* r, int k0, int kc) {
        const int c = k0 + kc * 16 + 2 * t;
        r[0] = *(const float2*)(Srow0 + c);
        r[1] = *(const float2*)(Srow1 + c);
        r[2] = *(const float2*)(Srow0 + c + 8);
        r[3] = *(const float2*)(Srow1 + c + 8);
    };

    float acc[4][4] = {};
    const int it0 = kh * 8;

    issueV(it0, 0); CP_COMMIT();
    issueV(it0 + 1, 1); CP_COMMIT();

    for (int ii = 0; ii < 8; ++ii) {
        const int it = it0 + ii;
        const int k0 = it * 128;
        const int cur = ii & 1;
        CP_WAIT1();
        __syncthreads();

        const __nv_bfloat16* pVh = Vh + cur * 64 * CSP;
        const __nv_bfloat16* pVl = Vl + cur * 64 * CSP;

        float2 fr[2][4];
        ldfrag(fr[0], k0, 0);
#pragma unroll
        for (int kc = 0; kc < 8; ++kc) {
            if (kc < 7) ldfrag(fr[(kc + 1) & 1], k0, kc + 1);
            float2* r = fr[kc & 1];

            float2 p0, p1, p2, p3;
            p0.x = __expf(r[0].x - mr0) * invl0;  p0.y = __expf(r[0].y - mr0) * invl0;
            p1.x = __expf(r[1].x - mr1) * invl1;  p1.y = __expf(r[1].y - mr1) * invl1;
            p2.x = __expf(r[2].x - mr0) * invl0;  p2.y = __expf(r[2].y - mr0) * invl0;
            p3.x = __expf(r[3].x - mr1) * invl1;  p3.y = __expf(r[3].y - mr1) * invl1;
            if (wn == 0) {
                const int c = k0 + kc * 16 + 2 * t;
                *(float2*)(Wrow0 + c)     = p0;
                *(float2*)(Wrow1 + c)     = p1;
                *(float2*)(Wrow0 + c + 8) = p2;
                *(float2*)(Wrow1 + c + 8) = p3;
            }
            uint32_t ah0, ah1, ah2, ah3, al0, al1, al2, al3;
            split2(p0, ah0, al0);
            split2(p1, ah1, al1);
            split2(p2, ah2, al2);
            split2(p3, ah3, al3);

            const int kb = kc * 16;
#pragma unroll
            for (int nn = 0; nn < 4; ++nn) {
                int rb = wn * 32 + nn * 8 + g;
                uint32_t b0 = *(const uint32_t*)&pVh[rb * CSP + kb + 2 * t];
                uint32_t b1 = *(const uint32_t*)&pVh[rb * CSP + kb + 2 * t + 8];
                uint32_t c0 = *(const uint32_t*)&pVl[rb * CSP + kb + 2 * t];
                uint32_t c1 = *(const uint32_t*)&pVl[rb * CSP + kb + 2 * t + 8];
                mma16816(acc[nn], ah0, ah1, ah2, ah3, b0, b1);
                mma16816(acc[nn], ah0, ah1, ah2, ah3, c0, c1);
                mma16816(acc[nn], al0, al1, al2, al3, b0, b1);
            }
        }

        __syncthreads();
        if (ii + 2 < 8) issueV(it + 2, cur);
        CP_COMMIT();
    }

#pragma unroll
    for (int nn = 0; nn < 4; ++nn)
#pragma unroll
        for (int i2 = 0; i2 < 2; ++i2) {
            int s = m0 + wm * 16 + g + i2 * 8;
            int d = wn * 32 + nn * 8 + 2 * t;
            size_t idx = (size_t)(b * SEQ + s) * DMODEL + h * HDIM + d;
            float2 st = {acc[nn][i2 * 2 + 0], acc[nn][i2 * 2 + 1]};
            *(float2*)&cpart[(size_t)kh * XN + idx] = st;
        }
}

// ---------------------------------------------------------------------------
__global__ void combine_ctx(const float* __restrict__ cp,
                            __nv_bfloat16* __restrict__ ch,
                            __nv_bfloat16* __restrict__ cl)
{
    int i = blockIdx.x * 256 + threadIdx.x;
    float4 aa = ((const float4*)cp)[i];
    float4 bb = ((const float4*)(cp + XN))[i];
    aa.x += bb.x; aa.y += bb.y; aa.z += bb.z; aa.w += bb.w;
    splitstore(ch + 4 * (size_t)i, cl + 4 * (size_t)i, aa);
}

// ---------------------------------------------------------------------------
extern "C" void kernel_launch(void* const* d_in, const int* in_sizes, int n_in,
                              void* d_out, int out_size)
{
    const float* xin[3] = {(const float*)d_in[0], (const float*)d_in[1], (const float*)d_in[2]};
    const float* mask = (const float*)d_in[3];
    const float* Wg[4] = {(const float*)d_in[4], (const float*)d_in[6],
                          (const float*)d_in[8], (const float*)d_in[10]};
    const float* bg[4] = {(const float*)d_in[5], (const float*)d_in[7],
                          (const float*)d_in[9], (const float*)d_in[11]};

    __nv_bfloat16 *p_xh[3], *p_xl[3], *p_wh[4], *p_wl[4];
    __nv_bfloat16 *p_Qh, *p_Ql, *p_Kh, *p_Kl, *p_Vh, *p_Vl, *p_ch, *p_cl;
    float *p_ssc, *p_wsc, *p_osc, *p_cp;
    float2* p_ps;
    {
        __nv_bfloat16 *base_h, *base_l;
        cudaGetSymbolAddress((void**)&base_h, g_xh);
        cudaGetSymbolAddress((void**)&base_l, g_xl);
        for (int i = 0; i < 3; ++i) { p_xh[i] = base_h + (size_t)i * XN; p_xl[i] = base_l + (size_t)i * XN; }
        cudaGetSymbolAddress((void**)&base_h, g_wh);
        cudaGetSymbolAddress((void**)&base_l, g_wl);
        for (int i = 0; i < 4; ++i) { p_wh[i] = base_h + (size_t)i * WNN; p_wl[i] = base_l + (size_t)i * WNN; }
    }
    cudaGetSymbolAddress((void**)&p_Qh, g_Qh); cudaGetSymbolAddress((void**)&p_Ql, g_Ql);
    cudaGetSymbolAddress((void**)&p_Kh, g_Kh); cudaGetSymbolAddress((void**)&p_Kl, g_Kl);
    cudaGetSymbolAddress((void**)&p_Vh, g_Vh); cudaGetSymbolAddress((void**)&p_Vl, g_Vl);
    cudaGetSymbolAddress((void**)&p_ch, g_ch); cudaGetSymbolAddress((void**)&p_cl, g_cl);
    cudaGetSymbolAddress((void**)&p_cp, g_cp);
    cudaGetSymbolAddress((void**)&p_ps, g_ps);
    cudaGetSymbolAddress((void**)&p_ssc, g_ssc);
    cudaGetSymbolAddress((void**)&p_wsc, g_wsc);
    cudaGetSymbolAddress((void**)&p_osc, g_osc);

    float* outp;
    float* wp;
    long long osz = (long long)out_size;
    if (osz >= OUT_ELEMS + W_ELEMS) {
        outp = (float*)d_out;
        wp   = (float*)d_out + OUT_ELEMS;
    } else if (osz == W_ELEMS) {
        wp   = (float*)d_out;
        outp = p_osc;
    } else {
        outp = (float*)d_out;
        wp   = p_wsc;
    }

    cudaFuncSetAttribute(gemm_bf3<5>, cudaFuncAttributeMaxDynamicSharedMemorySize, 81920);
    cudaFuncSetAttribute(gemm_bf3<2>, cudaFuncAttributeMaxDynamicSharedMemorySize, 81920);
    cudaFuncSetAttribute(gemm_bf3<1>, cudaFuncAttributeMaxDynamicSharedMemorySize, 81920);
    cudaFuncSetAttribute(ctx_kernel, cudaFuncAttributeMaxDynamicSharedMemorySize, 69632);

    SplitArgs sa;
    for (int i = 0; i < 3; ++i)
        sa.seg[i] = SplitSeg{xin[i], p_xh[i], p_xl[i], XN / 4};
    for (int i = 0; i < 4; ++i)
        sa.seg[3 + i] = SplitSeg{Wg[i], p_wh[i], p_wl[i], WNN / 4};
    split_all<<<dim3(XN / 4 / 256, 7), 256>>>(sa);

    ProjArgs pa = {};
    for (int i = 0; i < 3; ++i) {
        pa.Ah[i] = p_xh[i]; pa.Al[i] = p_xl[i];
        pa.Bh[i] = p_wh[i]; pa.Bl[i] = p_wl[i];
        pa.bias[i] = bg[i];
    }
    pa.oh[0] = p_Qh; pa.ol[0] = p_Ql;
    pa.oh[1] = p_Kh; pa.ol[1] = p_Kl;
    pa.oh[2] = p_Vh; pa.ol[2] = p_Vl;
    ProjArgs pa0 = {};

    // Fused Q/K/V projections
    gemm_bf3<5><<<dim3(ROWS / 128, DMODEL / 128, 3), 256, 81920>>>(
        nullptr, nullptr, nullptr, nullptr, DMODEL, DMODEL, DMODEL,
        nullptr, nullptr, nullptr, nullptr, pa);

    // Raw scores -> SSC + partial stats
    gemm_bf3<2><<<dim3(SEQ / 128, SEQ / 128, BH), 256, 81920>>>(
        p_Qh, p_Ql, p_Kh, p_Kl, HDIM, HDIM, HDIM,
        p_ssc, nullptr, mask, p_ps, pa0);

    // Normalize SSC -> weights (wp) + split-K partial ctx
    ctx_kernel<<<dim3(SEQ / 64, 2, BH), 256, 69632>>>(
        p_ssc, wp, p_Vh, p_Vl, p_ps, p_cp);

    combine_ctx<<<XN / 4 / 256, 256>>>(p_cp, p_ch, p_cl);

    // Output projection
    gemm_bf3<1><<<dim3(ROWS / 128, DMODEL / 128, 1), 256, 81920>>>(
        p_ch, p_cl, p_wh[3], p_wl[3], DMODEL, DMODEL, DMODEL,
        outp, bg[3], nullptr, nullptr, pa0);
}

// round 12
// speedup vs baseline: 1.1643x; 1.1643x over previous
#include <cuda_runtime.h>
#include <cuda_bf16.h>
#include <math.h>
#include <stdint.h>

#define HEADS   12
#define DMODEL  768
#define HDIM    64
#define BATCH   2
#define SEQ     2048
#define ROWS    4096
#define BH      24
#define NEGBIG  (-3.402823e38f)

static const long long OUT_ELEMS = (long long)ROWS * DMODEL;
static const long long W_ELEMS   = (long long)BH * SEQ * SEQ;

#define XN (ROWS * DMODEL)
#define WNN (DMODEL * DMODEL)

// Scratch (device globals: allocation-free)
__device__ __nv_bfloat16 g_xh[3][XN], g_xl[3][XN];
__device__ __nv_bfloat16 g_wh[4][WNN], g_wl[4][WNN];
__device__ __nv_bfloat16 g_Qh[XN], g_Ql[XN];
__device__ __nv_bfloat16 g_Kh[XN], g_Kl[XN];
__device__ __nv_bfloat16 g_Vh[XN], g_Vl[XN];         // [b,h,dh,s]
__device__ __nv_bfloat16 g_ch[XN], g_cl[XN];
__device__ float  g_cp[2][XN];
__device__ float2 g_ps[BH * 16 * SEQ];
__device__ float  g_wsc[(long long)BH * SEQ * SEQ];
__device__ float  g_osc[XN];

struct ProjArgs {
    const __nv_bfloat16 *Ah[3], *Al[3], *Bh[3], *Bl[3];
    const float* bias[3];
    __nv_bfloat16 *oh[3], *ol[3];
};
struct SplitSeg { const float* src; __nv_bfloat16* hi; __nv_bfloat16* lo; int n4; };
struct SplitArgs { SplitSeg seg[7]; };

__device__ __forceinline__ uint32_t smem_u32(const void* p) {
    return (uint32_t)__cvta_generic_to_shared(p);
}
__device__ __forceinline__ void cpa16(uint32_t d, const void* s) {
    asm volatile("cp.async.cg.shared.global [%0], [%1], 16;" :: "r"(d), "l"(s));
}
#define CP_COMMIT() asm volatile("cp.async.commit_group;")
#define CP_WAIT1()  asm volatile("cp.async.wait_group 1;")

__device__ __forceinline__ void mma16816(float* c,
                                         uint32_t a0, uint32_t a1, uint32_t a2, uint32_t a3,
                                         uint32_t b0, uint32_t b1)
{
    asm volatile(
        "mma.sync.aligned.m16n8k16.row.col.f32.bf16.bf16.f32 "
        "{%0,%1,%2,%3}, {%4,%5,%6,%7}, {%8,%9}, {%0,%1,%2,%3};\n"
        : "+f"(c[0]), "+f"(c[1]), "+f"(c[2]), "+f"(c[3])
        : "r"(a0), "r"(a1), "r"(a2), "r"(a3), "r"(b0), "r"(b1));
}

__device__ __forceinline__ void splitstore(__nv_bfloat16* ph, __nv_bfloat16* pl, float4 f)
{
    float xs[4] = {f.x, f.y, f.z, f.w};
#pragma unroll
    for (int p = 0; p < 2; ++p) {
        float x0 = xs[2 * p], x1 = xs[2 * p + 1];
        __nv_bfloat16 h0 = __float2bfloat16(x0);
        __nv_bfloat16 h1 = __float2bfloat16(x1);
        __nv_bfloat16 l0 = __float2bfloat16(x0 - __bfloat162float(h0));
        __nv_bfloat16 l1 = __float2bfloat16(x1 - __bfloat162float(h1));
        __nv_bfloat162 vh; vh.x = h0; vh.y = h1;
        __nv_bfloat162 vl; vl.x = l0; vl.y = l1;
        *(__nv_bfloat162*)(ph + 2 * p) = vh;
        *(__nv_bfloat162*)(pl + 2 * p) = vl;
    }
}

// ---------------------------------------------------------------------------
__global__ void split_all(SplitArgs a)
{
    const SplitSeg s = a.seg[blockIdx.y];
    int i = blockIdx.x * 256 + threadIdx.x;
    if (i >= s.n4) return;
    float4 f = ((const float4*)s.src)[i];
    splitstore(s.hi + 4 * (size_t)i, s.lo + 4 * (size_t)i, f);
}

// ---------------------------------------------------------------------------
// Unified bf16x3 GEMM, cp.async double-buffered. C = A[M,K] @ B[N,K]^T.
// Tile 128x128x32, 8 warps (2 m x 4 n).
// MODE 1: fp32 out + bias. MODE 2: scores (scale, mask, S + pstat).
// MODE 5: QKV fused (z), outputs pre-split hi/lo; z==2 transposed V.
// ---------------------------------------------------------------------------
#define SP 40

template<int MODE>
__global__ void __launch_bounds__(256)
gemm_bf3(const __nv_bfloat16* __restrict__ Ahg, const __nv_bfloat16* __restrict__ Alg,
         const __nv_bfloat16* __restrict__ Bhg, const __nv_bfloat16* __restrict__ Blg,
         int lda, int ldb, int K,
         float* __restrict__ Cg, const float* __restrict__ biasg,
         const float* __restrict__ maskg, float2* __restrict__ pstat,
         ProjArgs pa)
{
    extern __shared__ __align__(16) char smraw[];
    __nv_bfloat16* sAh = (__nv_bfloat16*)smraw;
    __nv_bfloat16* sAl = sAh + 2 * 128 * SP;
    __nv_bfloat16* sBh = sAl + 2 * 128 * SP;
    __nv_bfloat16* sBl = sBh + 2 * 128 * SP;

    const int tid = threadIdx.x;
    const int wid = tid >> 5, lane = tid & 31;
    const int g = lane >> 2, t = lane & 3;
    const int wm = wid & 1, wn = wid >> 1;
    const int m0 = blockIdx.x * 128, n0 = blockIdx.y * 128;
    const int z  = blockIdx.z;

    const __nv_bfloat16 *Ah, *Al, *Bh, *Bl;
    const float* biasp = biasg;
    if (MODE == 5) {
        Ah = pa.Ah[z]; Al = pa.Al[z]; Bh = pa.Bh[z]; Bl = pa.Bl[z]; biasp = pa.bias[z];
    } else if (MODE == 2) {
        size_t off = (size_t)z * SEQ * HDIM;
        Ah = Ahg + off; Al = Alg + off; Bh = Bhg + off; Bl = Blg + off;
    } else {
        Ah = Ahg; Al = Alg; Bh = Bhg; Bl = Blg;
    }

    const int lrow = tid >> 1;
    const int lch  = (tid & 1) * 2;

    auto issue = [&](int kt, int stg) {
        const int k0 = kt * 32;
        const __nv_bfloat16* gah = Ah + (size_t)(m0 + lrow) * lda + k0 + lch * 8;
        const __nv_bfloat16* gal = Al + (size_t)(m0 + lrow) * lda + k0 + lch * 8;
        const __nv_bfloat16* gbh = Bh + (size_t)(n0 + lrow) * ldb + k0 + lch * 8;
        const __nv_bfloat16* gbl = Bl + (size_t)(n0 + lrow) * ldb + k0 + lch * 8;
        uint32_t o = (uint32_t)((stg * 128 + lrow) * SP + lch * 8) * 2;
        uint32_t dah = smem_u32(sAh) + o, dal = smem_u32(sAl) + o;
        uint32_t dbh = smem_u32(sBh) + o, dbl = smem_u32(sBl) + o;
        cpa16(dah, gah); cpa16(dah + 16, gah + 8);
        cpa16(dal, gal); cpa16(dal + 16, gal + 8);
        cpa16(dbh, gbh); cpa16(dbh + 16, gbh + 8);
        cpa16(dbl, gbl); cpa16(dbl + 16, gbl + 8);
    };

    float acc[4][4][4] = {};

    auto compute = [&](int stg) {
        const __nv_bfloat16* pAh = sAh + stg * 128 * SP;
        const __nv_bfloat16* pAl = sAl + stg * 128 * SP;
        const __nv_bfloat16* pBh = sBh + stg * 128 * SP;
        const __nv_bfloat16* pBl = sBl + stg * 128 * SP;
#pragma unroll
        for (int kb = 0; kb < 32; kb += 16) {
            uint32_t ah[4][4], al[4][4];
#pragma unroll
            for (int f = 0; f < 4; ++f) {
                int rbase = wm * 64 + f * 16 + g;
#pragma unroll
                for (int j = 0; j < 4; ++j) {
                    int rr = rbase + (j & 1) * 8;
                    int cc = kb + 2 * t + (j >> 1) * 8;
                    ah[f][j] = *(const uint32_t*)&pAh[rr * SP + cc];
                    al[f][j] = *(const uint32_t*)&pAl[rr * SP + cc];
                }
            }
#pragma unroll
            for (int nn = 0; nn < 4; ++nn) {
                int rb = wn * 32 + nn * 8 + g;
                uint32_t b0 = *(const uint32_t*)&pBh[rb * SP + kb + 2 * t];
                uint32_t b1 = *(const uint32_t*)&pBh[rb * SP + kb + 2 * t + 8];
                uint32_t c0 = *(const uint32_t*)&pBl[rb * SP + kb + 2 * t];
                uint32_t c1 = *(const uint32_t*)&pBl[rb * SP + kb + 2 * t + 8];
#pragma unroll
                for (int f = 0; f < 4; ++f) {
                    mma16816(acc[f][nn], ah[f][0], ah[f][1], ah[f][2], ah[f][3], b0, b1);
                    mma16816(acc[f][nn], ah[f][0], ah[f][1], ah[f][2], ah[f][3], c0, c1);
                    mma16816(acc[f][nn], al[f][0], al[f][1], al[f][2], al[f][3], b0, b1);
                }
            }
        }
    };

    const int nk = K / 32;
    issue(0, 0); CP_COMMIT();
    if (nk > 1) issue(1, 1);
    CP_COMMIT();
    for (int kt = 0; kt < nk; ++kt) {
        int cur = kt & 1;
        CP_WAIT1();
        __syncthreads();
        compute(cur);
        __syncthreads();
        if (kt + 2 < nk) issue(kt + 2, cur);
        CP_COMMIT();
    }

    // ---------------- epilogues ----------------
    if (MODE == 1) {
#pragma unroll
        for (int f = 0; f < 4; ++f)
#pragma unroll
            for (int nn = 0; nn < 4; ++nn)
#pragma unroll
                for (int i2 = 0; i2 < 2; ++i2) {
                    int m = m0 + wm * 64 + f * 16 + g + i2 * 8;
                    int n = n0 + wn * 32 + nn * 8 + 2 * t;
                    float2 st = {acc[f][nn][i2 * 2 + 0] + biasp[n],
                                 acc[f][nn][i2 * 2 + 1] + biasp[n + 1]};
                    *(float2*)&Cg[(size_t)m * DMODEL + n] = st;
                }
    } else if (MODE == 5) {
#pragma unroll
        for (int f = 0; f < 4; ++f)
#pragma unroll
            for (int nn = 0; nn < 4; ++nn)
#pragma unroll
                for (int i2 = 0; i2 < 2; ++i2) {
                    int m = m0 + wm * 64 + f * 16 + g + i2 * 8;
                    int n = n0 + wn * 32 + nn * 8 + 2 * t;
                    float v0 = acc[f][nn][i2 * 2 + 0] + biasp[n];
                    float v1 = acc[f][nn][i2 * 2 + 1] + biasp[n + 1];
                    int b = m >> 11, s = m & 2047;
                    int h = n >> 6,  dh = n & 63;
                    __nv_bfloat16 h0 = __float2bfloat16(v0);
                    __nv_bfloat16 h1 = __float2bfloat16(v1);
                    __nv_bfloat16 l0 = __float2bfloat16(v0 - __bfloat162float(h0));
                    __nv_bfloat16 l1 = __float2bfloat16(v1 - __bfloat162float(h1));
                    if (z < 2) {
                        size_t idx = (((size_t)(b * HEADS + h)) * SEQ + s) * HDIM + dh;
                        __nv_bfloat162 hh; hh.x = h0; hh.y = h1;
                        __nv_bfloat162 ll; ll.x = l0; ll.y = l1;
                        *(__nv_bfloat162*)&pa.oh[z][idx] = hh;
                        *(__nv_bfloat162*)&pa.ol[z][idx] = ll;
                    } else {
                        size_t base = (((size_t)(b * HEADS + h)) * HDIM + dh) * SEQ + s;
                        pa.oh[2][base]       = h0;
                        pa.oh[2][base + SEQ] = h1;
                        pa.ol[2][base]       = l0;
                        pa.ol[2][base + SEQ] = l1;
                    }
                }
    } else { // MODE 2: scores + stats
        const int bidx = z / HEADS;
        float* S = Cg + (size_t)z * SEQ * SEQ;
        float mk[4][2];
#pragma unroll
        for (int nn = 0; nn < 4; ++nn) {
            int gc = n0 + wn * 32 + nn * 8 + 2 * t;
            mk[nn][0] = maskg[bidx * SEQ + gc];
            mk[nn][1] = maskg[bidx * SEQ + gc + 1];
        }
        float pm[8], pls[8];
#pragma unroll
        for (int f = 0; f < 4; ++f)
#pragma unroll
            for (int i2 = 0; i2 < 2; ++i2) {
                int sl = f * 2 + i2;
                int rowl = wm * 64 + f * 16 + g + i2 * 8;
                float vb[8]; bool ok[8];
                float tm = NEGBIG;
#pragma unroll
                for (int nn = 0; nn < 4; ++nn) {
                    int gc = n0 + wn * 32 + nn * 8 + 2 * t;
                    float v0 = acc[f][nn][i2 * 2 + 0] * 0.125f;
                    float v1 = acc[f][nn][i2 * 2 + 1] * 0.125f;
                    bool o0 = (mk[nn][0] == 0.0f);
                    bool o1 = (mk[nn][1] == 0.0f);
                    float2 st;
                    st.x = o0 ? v0 : -INFINITY;
                    st.y = o1 ? v1 : -INFINITY;
                    *(float2*)&S[(size_t)(m0 + rowl) * SEQ + gc] = st;
                    vb[nn * 2 + 0] = v0; ok[nn * 2 + 0] = o0;
                    vb[nn * 2 + 1] = v1; ok[nn * 2 + 1] = o1;
                    if (o0) tm = fmaxf(tm, v0);
                    if (o1) tm = fmaxf(tm, v1);
                }
                float tl = 0.f;
#pragma unroll
                for (int j = 0; j < 8; ++j)
                    if (ok[j]) tl += __expf(vb[j] - tm);
                pm[sl] = tm; pls[sl] = tl;
            }
#pragma unroll
        for (int off2 = 1; off2 <= 2; off2 <<= 1)
#pragma unroll
            for (int sl = 0; sl < 8; ++sl) {
                float om = __shfl_xor_sync(0xffffffffu, pm[sl], off2);
                float ol = __shfl_xor_sync(0xffffffffu, pls[sl], off2);
                float nm = fmaxf(pm[sl], om);
                pls[sl] = pls[sl] * __expf(pm[sl] - nm) + ol * __expf(om - nm);
                pm[sl] = nm;
            }
        float2* sred = (float2*)smraw;
        __syncthreads();
        if (t == 0) {
#pragma unroll
            for (int f = 0; f < 4; ++f)
#pragma unroll
                for (int i2 = 0; i2 < 2; ++i2) {
                    int rowl = wm * 64 + f * 16 + g + i2 * 8;
                    sred[wn * 128 + rowl] = make_float2(pm[f * 2 + i2], pls[f * 2 + i2]);
                }
        }
        __syncthreads();
        if (tid < 128) {
            float m = NEGBIG, l = 0.f;
#pragma unroll
            for (int w = 0; w < 4; ++w) {
                float2 p = sred[w * 128 + tid];
                float nm = fmaxf(m, p.x);
                l = l * __expf(m - nm) + p.y * __expf(p.x - nm);
                m = nm;
            }
            pstat[((size_t)z * 16 + blockIdx.y) * SEQ + m0 + tid] = make_float2(m, l);
        }
    }
}

// ---------------------------------------------------------------------------
// ctx split-K: stats combined in-kernel; normalize raw S -> final weights
// (in place, same-thread read/write) + partial ctx. BM=64, BK=64 (54KB smem
// -> 3 CTAs/SM), 16 k-iters per CTA.
// ---------------------------------------------------------------------------
#define CS2 72

__global__ void __launch_bounds__(256, 3)
ctx_kernel(float* __restrict__ W_, const __nv_bfloat16* __restrict__ vh_g,
           const __nv_bfloat16* __restrict__ vl_g,
           const float2* __restrict__ pstat,
           float* __restrict__ cpart)
{
    extern __shared__ __align__(16) char smraw[];
    __nv_bfloat16* Ph = (__nv_bfloat16*)smraw;          // [64][CS2]
    __nv_bfloat16* Pl = Ph + 64 * CS2;
    __nv_bfloat16* Vh = Pl + 64 * CS2;                  // [2][64][CS2]
    __nv_bfloat16* Vl = Vh + 2 * 64 * CS2;

    const int z = blockIdx.z;
    const int kh = blockIdx.y;
    const int b = z / HEADS, h = z % HEADS;
    const int m0 = blockIdx.x * 64;
    float* S = W_ + (size_t)z * SEQ * SEQ;
    const __nv_bfloat16* Vhp = vh_g + (size_t)z * HDIM * SEQ;
    const __nv_bfloat16* Vlp = vl_g + (size_t)z * HDIM * SEQ;

    const int tid = threadIdx.x;
    const int wid = tid >> 5, lane = tid & 31;
    const int g = lane >> 2, t = lane & 3;
    const int wm = wid >> 1, wn = wid & 1;
    const int lr = tid >> 2, q4 = tid & 3;

    // Combine per-column-block stats for this thread's row (same order as
    // the reduce_stats kernel).
    float mr = NEGBIG, lsum = 0.f;
    {
        const float2* pr = pstat + (size_t)z * 16 * SEQ + m0 + lr;
#pragma unroll
        for (int cb = 0; cb < 16; ++cb) {
            float2 p = pr[(size_t)cb * SEQ];
            float nm = fmaxf(mr, p.x);
            lsum = lsum * __expf(mr - nm) + p.y * __expf(p.x - nm);
            mr = nm;
        }
    }
    const float invl = 1.0f / lsum;

    auto issueV = [&](int it, int stg) {
        const int k0 = it * 64;
        const __nv_bfloat16* gh = Vhp + (size_t)lr * SEQ + k0 + q4 * 16;
        const __nv_bfloat16* gl = Vlp + (size_t)lr * SEQ + k0 + q4 * 16;
        uint32_t o = (uint32_t)((stg * 64 + lr) * CS2 + q4 * 16) * 2;
        uint32_t dh_ = smem_u32(Vh) + o, dl_ = smem_u32(Vl) + o;
#pragma unroll
        for (int j = 0; j < 2; ++j) {
            cpa16(dh_ + j * 16, gh + j * 8);
            cpa16(dl_ + j * 16, gl + j * 8);
        }
    };

    float4 sreg[4];
    auto loadS = [&](int it) {
        const float* srow = S + (size_t)(m0 + lr) * SEQ + it * 64;
#pragma unroll
        for (int j = 0; j < 4; ++j)
            sreg[j] = *(const float4*)(srow + (q4 + 4 * j) * 4);
    };
    auto procS = [&](int it) {
        float* srow = S + (size_t)(m0 + lr) * SEQ + it * 64;
#pragma unroll
        for (int j = 0; j < 4; ++j) {
            int c = (q4 + 4 * j) * 4;
            float4 f = sreg[j];
            f.x = __expf(f.x - mr) * invl;
            f.y = __expf(f.y - mr) * invl;
            f.z = __expf(f.z - mr) * invl;
            f.w = __expf(f.w - mr) * invl;
            *(float4*)(srow + c) = f;
            splitstore(Ph + lr * CS2 + c, Pl + lr * CS2 + c, f);
        }
    };

    float acc[4][4] = {};
    const int it0 = kh * 16;

    loadS(it0);
    issueV(it0, 0); CP_COMMIT();
    issueV(it0 + 1, 1); CP_COMMIT();

    for (int ii = 0; ii < 16; ++ii) {
        const int it = it0 + ii;
        int cur = ii & 1;
        procS(it);
        CP_WAIT1();
        __syncthreads();
        if (ii < 15) loadS(it + 1);

        const __nv_bfloat16* pVh = Vh + cur * 64 * CS2;
        const __nv_bfloat16* pVl = Vl + cur * 64 * CS2;
#pragma unroll
        for (int kc = 0; kc < 4; ++kc) {
            int kb = kc * 16;
            uint32_t ah[4], al4[4];
#pragma unroll
            for (int j = 0; j < 4; ++j) {
                int rr = wm * 16 + g + (j & 1) * 8;
                int cc = kb + 2 * t + (j >> 1) * 8;
                ah[j]  = *(const uint32_t*)&Ph[rr * CS2 + cc];
                al4[j] = *(const uint32_t*)&Pl[rr * CS2 + cc];
            }
#pragma unroll
            for (int nn = 0; nn < 4; ++nn) {
                int rb = wn * 32 + nn * 8 + g;
                uint32_t b0 = *(const uint32_t*)&pVh[rb * CS2 + kb + 2 * t];
                uint32_t b1 = *(const uint32_t*)&pVh[rb * CS2 + kb + 2 * t + 8];
                uint32_t c0 = *(const uint32_t*)&pVl[rb * CS2 + kb + 2 * t];
                uint32_t c1 = *(const uint32_t*)&pVl[rb * CS2 + kb + 2 * t + 8];
                mma16816(acc[nn], ah[0], ah[1], ah[2], ah[3], b0, b1);
                mma16816(acc[nn], ah[0], ah[1], ah[2], ah[3], c0, c1);
                mma16816(acc[nn], al4[0], al4[1], al4[2], al4[3], b0, b1);
            }
        }
        __syncthreads();
        if (ii + 2 < 16) issueV(it + 2, cur);
        CP_COMMIT();
    }

#pragma unroll
    for (int nn = 0; nn < 4; ++nn)
#pragma unroll
        for (int i2 = 0; i2 < 2; ++i2) {
            int s = m0 + wm * 16 + g + i2 * 8;
            int d = wn * 32 + nn * 8 + 2 * t;
            size_t idx = (size_t)(b * SEQ + s) * DMODEL + h * HDIM + d;
            float2 st = {acc[nn][i2 * 2 + 0], acc[nn][i2 * 2 + 1]};
            *(float2*)&cpart[(size_t)kh * XN + idx] = st;
        }
}

// ---------------------------------------------------------------------------
__global__ void combine_ctx(const float* __restrict__ cp,
                            __nv_bfloat16* __restrict__ ch,
                            __nv_bfloat16* __restrict__ cl)
{
    int i = blockIdx.x * 256 + threadIdx.x;
    float4 aa = ((const float4*)cp)[i];
    float4 bb = ((const float4*)(cp + XN))[i];
    aa.x += bb.x; aa.y += bb.y; aa.z += bb.z; aa.w += bb.w;
    splitstore(ch + 4 * (size_t)i, cl + 4 * (size_t)i, aa);
}

// ---------------------------------------------------------------------------
extern "C" void kernel_launch(void* const* d_in, const int* in_sizes, int n_in,
                              void* d_out, int out_size)
{
    const float* xin[3] = {(const float*)d_in[0], (const float*)d_in[1], (const float*)d_in[2]};
    const float* mask = (const float*)d_in[3];
    const float* Wg[4] = {(const float*)d_in[4], (const float*)d_in[6],
                          (const float*)d_in[8], (const float*)d_in[10]};
    const float* bg[4] = {(const float*)d_in[5], (const float*)d_in[7],
                          (const float*)d_in[9], (const float*)d_in[11]};

    __nv_bfloat16 *p_xh[3], *p_xl[3], *p_wh[4], *p_wl[4];
    __nv_bfloat16 *p_Qh, *p_Ql, *p_Kh, *p_Kl, *p_Vh, *p_Vl, *p_ch, *p_cl;
    float *p_wsc, *p_osc, *p_cp;
    float2* p_ps;
    {
        __nv_bfloat16 *base_h, *base_l;
        cudaGetSymbolAddress((void**)&base_h, g_xh);
        cudaGetSymbolAddress((void**)&base_l, g_xl);
        for (int i = 0; i < 3; ++i) { p_xh[i] = base_h + (size_t)i * XN; p_xl[i] = base_l + (size_t)i * XN; }
        cudaGetSymbolAddress((void**)&base_h, g_wh);
        cudaGetSymbolAddress((void**)&base_l, g_wl);
        for (int i = 0; i < 4; ++i) { p_wh[i] = base_h + (size_t)i * WNN; p_wl[i] = base_l + (size_t)i * WNN; }
    }
    cudaGetSymbolAddress((void**)&p_Qh, g_Qh); cudaGetSymbolAddress((void**)&p_Ql, g_Ql);
    cudaGetSymbolAddress((void**)&p_Kh, g_Kh); cudaGetSymbolAddress((void**)&p_Kl, g_Kl);
    cudaGetSymbolAddress((void**)&p_Vh, g_Vh); cudaGetSymbolAddress((void**)&p_Vl, g_Vl);
    cudaGetSymbolAddress((void**)&p_ch, g_ch); cudaGetSymbolAddress((void**)&p_cl, g_cl);
    cudaGetSymbolAddress((void**)&p_cp, g_cp);
    cudaGetSymbolAddress((void**)&p_ps, g_ps);
    cudaGetSymbolAddress((void**)&p_wsc, g_wsc);
    cudaGetSymbolAddress((void**)&p_osc, g_osc);

    float* outp;
    float* wp;
    long long osz = (long long)out_size;
    if (osz >= OUT_ELEMS + W_ELEMS) {
        outp = (float*)d_out;
        wp   = (float*)d_out + OUT_ELEMS;
    } else if (osz == W_ELEMS) {
        wp   = (float*)d_out;
        outp = p_osc;
    } else {
        outp = (float*)d_out;
        wp   = p_wsc;
    }

    cudaFuncSetAttribute(gemm_bf3<5>, cudaFuncAttributeMaxDynamicSharedMemorySize, 81920);
    cudaFuncSetAttribute(gemm_bf3<2>, cudaFuncAttributeMaxDynamicSharedMemorySize, 81920);
    cudaFuncSetAttribute(gemm_bf3<1>, cudaFuncAttributeMaxDynamicSharedMemorySize, 81920);
    cudaFuncSetAttribute(ctx_kernel, cudaFuncAttributeMaxDynamicSharedMemorySize, 55296);

    SplitArgs sa;
    for (int i = 0; i < 3; ++i)
        sa.seg[i] = SplitSeg{xin[i], p_xh[i], p_xl[i], XN / 4};
    for (int i = 0; i < 4; ++i)
        sa.seg[3 + i] = SplitSeg{Wg[i], p_wh[i], p_wl[i], WNN / 4};
    split_all<<<dim3(XN / 4 / 256, 7), 256>>>(sa);

    ProjArgs pa = {};
    for (int i = 0; i < 3; ++i) {
        pa.Ah[i] = p_xh[i]; pa.Al[i] = p_xl[i];
        pa.Bh[i] = p_wh[i]; pa.Bl[i] = p_wl[i];
        pa.bias[i] = bg[i];
    }
    pa.oh[0] = p_Qh; pa.ol[0] = p_Ql;
    pa.oh[1] = p_Kh; pa.ol[1] = p_Kl;
    pa.oh[2] = p_Vh; pa.ol[2] = p_Vl;
    ProjArgs pa0 = {};

    // Fused Q/K/V projections
    gemm_bf3<5><<<dim3(ROWS / 128, DMODEL / 128, 3), 256, 81920>>>(
        nullptr, nullptr, nullptr, nullptr, DMODEL, DMODEL, DMODEL,
        nullptr, nullptr, nullptr, nullptr, pa);

    // Raw scores + partial stats
    gemm_bf3<2><<<dim3(SEQ / 128, SEQ / 128, BH), 256, 81920>>>(
        p_Qh, p_Ql, p_Kh, p_Kl, HDIM, HDIM, HDIM,
        wp, nullptr, mask, p_ps, pa0);

    // Normalize (stats combined in-kernel) -> weights + split-K partial ctx
    ctx_kernel<<<dim3(SEQ / 64, 2, BH), 256, 55296>>>(
        wp, p_Vh, p_Vl, p_ps, p_cp);

    combine_ctx<<<XN / 4 / 256, 256>>>(p_cp, p_ch, p_cl);

    // Output projection
    gemm_bf3<1><<<dim3(ROWS / 128, DMODEL / 128, 1), 256, 81920>>>(
        p_ch, p_cl, p_wh[3], p_wl[3], DMODEL, DMODEL, DMODEL,
        outp, bg[3], nullptr, nullptr, pa0);
}